// round 16
// baseline (speedup 1.0000x reference)
#include <cuda_runtime.h>
#include <math.h>

#define Bc 8
#define Nc 16384
#define Cc 96
#define Hh 4
#define Dd 24
#define WIMG 128
#define NT 512
#define KVP 584          // kv_s per-head pitch
#define TT 64            // tokens per tile
#define NBLK 256         // tiles per batch
#define XQ 76            // pitch for 64-token tiles: 16B-aligned, bank stride 12

// rope: theta_k = 10000^(-k/48); angle = (n mod 128) * theta_k
#define THL 0.27682734124061354f   // log2(10000)/48

// ---- fused global scratch: [0,18432) = kv[b][h][24][24], [18432,19200) = ksum[b][96]
#define ACC_KV 0
#define ACC_KS 18432
#define ACC_SZ 19200
__device__ float g_accum[ACC_SZ];

typedef unsigned long long u64;

__device__ __forceinline__ u64 pk2(float lo, float hi) {
    u64 r; asm("mov.b64 %0,{%1,%2};" : "=l"(r) : "f"(lo), "f"(hi)); return r;
}
__device__ __forceinline__ void upk2(u64 v, float& lo, float& hi) {
    asm("mov.b64 {%0,%1},%2;" : "=f"(lo), "=f"(hi) : "l"(v));
}
__device__ __forceinline__ u64 fma2(u64 a, u64 b, u64 c) {
    u64 d; asm("fma.rn.f32x2 %0,%1,%2,%3;" : "=l"(d) : "l"(a), "l"(b), "l"(c)); return d;
}
__device__ __forceinline__ float elu1(float x) { return x > 0.f ? x + 1.f : __expf(x); }

// ---------------- K1: k-half GEMM + ksum + kv reduction (64-token tiles) ----------
// smem: x_s[96*XQ] | w_s[9216] | b_s[96] | kr_s[96*XQ]   (~93KB -> 2 CTAs/SM)
#define K1_SMEM ((7296 + 9216 + 96 + 7296) * 4)

__global__ void __launch_bounds__(NT, 2)
k_stats(const float* __restrict__ xg, const float* __restrict__ wg,
        const float* __restrict__ bg) {
    extern __shared__ float smem[];
    float* x_s  = smem;            // [c*XQ + t]
    float* w_s  = smem + 7296;     // [c*96 + j]
    float* b_s  = w_s + 9216;
    float* kr_s = b_s + 96;        // [c*XQ + t]

    int tid = threadIdx.x;
    int q = blockIdx.x, b = blockIdx.y;
    const float* xrow = xg + ((size_t)b * Nc + (size_t)q * TT) * Cc;
    int timg0 = (q & 1) * TT;      // image-w offset for rope

    for (int i = tid; i < TT * Cc; i += NT) {
        int t = i / Cc, c = i % Cc;
        x_s[c * XQ + t] = xrow[i];
    }
    for (int i = tid; i < Cc * Cc; i += NT) {
        int j = i / Cc, c = i % Cc;
        w_s[c * Cc + j] = wg[(Cc + j) * Cc + c];
    }
    if (tid < Cc) b_s[tid] = bg[Cc + tid];
    __syncthreads();

    // GEMM: warp owns 6 channels (broadcast w), lane owns 2 consecutive tokens
    int warp = tid >> 5, lane = tid & 31;
    int j0 = warp * 6, t0 = lane * 2;

    u64 acc[2][3];
#pragma unroll
    for (int tt = 0; tt < 2; tt++)
#pragma unroll
        for (int jj = 0; jj < 3; jj++)
            acc[tt][jj] = pk2(b_s[j0 + 2 * jj], b_s[j0 + 2 * jj + 1]);

#pragma unroll 4
    for (int c = 0; c < Cc; c++) {
        float2 xv2 = *(const float2*)&x_s[c * XQ + t0];
        const u64* wr = (const u64*)&w_s[c * Cc + j0];
        u64 w0 = wr[0], w1 = wr[1], w2 = wr[2];
        float xv[2] = {xv2.x, xv2.y};
#pragma unroll
        for (int tt = 0; tt < 2; tt++) {
            u64 xd = pk2(xv[tt], xv[tt]);
            acc[tt][0] = fma2(xd, w0, acc[tt][0]);
            acc[tt][1] = fma2(xd, w1, acc[tt][1]);
            acc[tt][2] = fma2(xd, w2, acc[tt][2]);
        }
    }

    // epilogue: elu+1, rope (MUFU), packed stores, warp-reduced ksum
#pragma unroll
    for (int jj = 0; jj < 3; jj++) {
        int ch = j0 + 2 * jj;
        int kk = ch >> 1;
        float theta = exp2f(-(float)kk * THL);
        float r0[2], r1[2];
        float s0 = 0.f, s1 = 0.f;
#pragma unroll
        for (int tt = 0; tt < 2; tt++) {
            float a0, a1; upk2(acc[tt][jj], a0, a1);
            float k0 = elu1(a0), k1 = elu1(a1);
            s0 += k0; s1 += k1;
            float a = (float)(timg0 + t0 + tt) * theta;
            float sv = __sinf(a), cv = __cosf(a);
            r0[tt] = k0 * cv - k1 * sv;
            r1[tt] = k0 * sv + k1 * cv;
        }
        *(float2*)&kr_s[ch * XQ + t0]       = make_float2(r0[0], r0[1]);
        *(float2*)&kr_s[(ch + 1) * XQ + t0] = make_float2(r1[0], r1[1]);
#pragma unroll
        for (int off = 16; off; off >>= 1) {
            s0 += __shfl_xor_sync(0xffffffffu, s0, off);
            s1 += __shfl_xor_sync(0xffffffffu, s1, off);
        }
        if (lane == 0) {
            atomicAdd(&g_accum[ACC_KS + b * Cc + ch], s0);
            atomicAdd(&g_accum[ACC_KS + b * Cc + ch + 1], s1);
        }
    }
    __syncthreads();

    // kv: 4 heads x 128 threads; each thread 3x3 cells over 32 tokens (float4)
    int h = tid >> 7, qq = tid & 127;
    int cell = qq & 63, half = qq >> 6;
    int d0 = (cell & 7) * 3, e0 = (cell >> 3) * 3;
    int tq0 = half * 32;
    u64 a2[3][3];
#pragma unroll
    for (int i = 0; i < 3; i++)
#pragma unroll
        for (int j = 0; j < 3; j++) a2[i][j] = 0ull;

    const float* krb = &kr_s[(h * Dd + d0) * XQ + tq0];
    const float* xb  = &x_s[(h * Dd + e0) * XQ + tq0];
#pragma unroll 2
    for (int i = 0; i < 8; i++) {
        float4 kA = *(const float4*)&krb[4 * i];
        float4 kB = *(const float4*)&krb[XQ + 4 * i];
        float4 kC = *(const float4*)&krb[2 * XQ + 4 * i];
        float4 xA = *(const float4*)&xb[4 * i];
        float4 xB = *(const float4*)&xb[XQ + 4 * i];
        float4 xC = *(const float4*)&xb[2 * XQ + 4 * i];
        u64 kr0a = pk2(kA.x, kA.y), kr0b = pk2(kA.z, kA.w);
        u64 kr1a = pk2(kB.x, kB.y), kr1b = pk2(kB.z, kB.w);
        u64 kr2a = pk2(kC.x, kC.y), kr2b = pk2(kC.z, kC.w);
        u64 xv0a = pk2(xA.x, xA.y), xv0b = pk2(xA.z, xA.w);
        u64 xv1a = pk2(xB.x, xB.y), xv1b = pk2(xB.z, xB.w);
        u64 xv2a = pk2(xC.x, xC.y), xv2b = pk2(xC.z, xC.w);
        a2[0][0] = fma2(kr0a, xv0a, a2[0][0]); a2[0][0] = fma2(kr0b, xv0b, a2[0][0]);
        a2[0][1] = fma2(kr0a, xv1a, a2[0][1]); a2[0][1] = fma2(kr0b, xv1b, a2[0][1]);
        a2[0][2] = fma2(kr0a, xv2a, a2[0][2]); a2[0][2] = fma2(kr0b, xv2b, a2[0][2]);
        a2[1][0] = fma2(kr1a, xv0a, a2[1][0]); a2[1][0] = fma2(kr1b, xv0b, a2[1][0]);
        a2[1][1] = fma2(kr1a, xv1a, a2[1][1]); a2[1][1] = fma2(kr1b, xv1b, a2[1][1]);
        a2[1][2] = fma2(kr1a, xv2a, a2[1][2]); a2[1][2] = fma2(kr1b, xv2b, a2[1][2]);
        a2[2][0] = fma2(kr2a, xv0a, a2[2][0]); a2[2][0] = fma2(kr2b, xv0b, a2[2][0]);
        a2[2][1] = fma2(kr2a, xv1a, a2[2][1]); a2[2][1] = fma2(kr2b, xv1b, a2[2][1]);
        a2[2][2] = fma2(kr2a, xv2a, a2[2][2]); a2[2][2] = fma2(kr2b, xv2b, a2[2][2]);
    }
    float* kvb_g = &g_accum[ACC_KV + ((size_t)b * Hh + h) * Dd * Dd];
#pragma unroll
    for (int i = 0; i < 3; i++)
#pragma unroll
        for (int j = 0; j < 3; j++) {
            float lo, hi; upk2(a2[i][j], lo, hi);
            atomicAdd(&kvb_g[(d0 + i) * Dd + e0 + j], lo + hi);
        }
}

// ---------------- K2: q-half GEMM + z + matvec(kv) + store (64-token tiles) -------
// smem: x_s[7296] | w_s[9216] | qr_s[7296] | kv_s[4*KVP] | b_s[96] | za[256]
#define K2_SMEM ((7296 + 9216 + 7296 + 4 * KVP + 96 + 256) * 4)

__global__ void __launch_bounds__(NT, 2)
k_out(const float* __restrict__ xg, const float* __restrict__ wg,
      const float* __restrict__ bg, float* __restrict__ og) {
    extern __shared__ float smem[];
    float* x_s  = smem;           // [c*XQ + t]
    float* w_s  = smem + 7296;    // [c*96 + j]
    float* qr_s = smem + 16512;   // [c*XQ + t]
    float* kv_s = qr_s + 7296;    // [4][KVP]
    float* b_s  = kv_s + 4 * KVP;
    float* za   = b_s + 96;       // [64][4]

    int tid = threadIdx.x;
    int q = blockIdx.x, bb = blockIdx.y;
    const float* xrow = xg + ((size_t)bb * Nc + (size_t)q * TT) * Cc;
    int timg0 = (q & 1) * TT;

    for (int i = tid; i < TT * Cc; i += NT) {
        int t = i / Cc, c = i % Cc;
        x_s[c * XQ + t] = xrow[i];
    }
    for (int i = tid; i < Cc * Cc; i += NT) {
        int j = i / Cc, c = i % Cc;
        w_s[c * Cc + j] = wg[j * Cc + c];
    }
    if (tid < Cc) b_s[tid] = bg[tid];
    if (tid < 256) za[tid] = 0.f;
    for (int i = tid; i < Hh * Dd * Dd; i += NT)
        kv_s[(i / 576) * KVP + (i % 576)] =
            g_accum[ACC_KV + (size_t)bb * Hh * Dd * Dd + i];
    __syncthreads();

    // j-fastest: 16 j-groups x 32 t-groups of 2 tokens
    int g_j = tid & 15, g_t = tid >> 4;
    int j0 = g_j * 6, t0 = g_t * 2;
    int head = j0 / Dd, e0 = j0 % Dd;

    u64 acc[2][3];
#pragma unroll
    for (int tt = 0; tt < 2; tt++)
#pragma unroll
        for (int jj = 0; jj < 3; jj++)
            acc[tt][jj] = pk2(b_s[j0 + 2 * jj], b_s[j0 + 2 * jj + 1]);

#pragma unroll 4
    for (int c = 0; c < Cc; c++) {
        float2 xv2 = *(const float2*)&x_s[c * XQ + t0];
        const u64* wr = (const u64*)&w_s[c * Cc + j0];
        u64 w0 = wr[0], w1 = wr[1], w2 = wr[2];
        float xv[2] = {xv2.x, xv2.y};
#pragma unroll
        for (int tt = 0; tt < 2; tt++) {
            u64 xd = pk2(xv[tt], xv[tt]);
            acc[tt][0] = fma2(xd, w0, acc[tt][0]);
            acc[tt][1] = fma2(xd, w1, acc[tt][1]);
            acc[tt][2] = fma2(xd, w2, acc[tt][2]);
        }
    }

    // epilogue: elu+1, z partial vs k_mean, rope (MUFU), write q_rope
    const float inv_n = 1.f / (float)Nc;
    float km[6];
#pragma unroll
    for (int i = 0; i < 6; i++) km[i] = g_accum[ACC_KS + bb * Cc + j0 + i] * inv_n;

    float zp[2] = {0.f, 0.f};
#pragma unroll
    for (int jj = 0; jj < 3; jj++) {
        int ch = j0 + 2 * jj;
        int kk = ch >> 1;
        float theta = exp2f(-(float)kk * THL);
        float r0[2], r1[2];
#pragma unroll
        for (int tt = 0; tt < 2; tt++) {
            float a0, a1; upk2(acc[tt][jj], a0, a1);
            float q0 = elu1(a0), q1 = elu1(a1);
            zp[tt] += q0 * km[2 * jj] + q1 * km[2 * jj + 1];
            float a = (float)(timg0 + t0 + tt) * theta;
            float sv = __sinf(a), cv = __cosf(a);
            r0[tt] = q0 * cv - q1 * sv;
            r1[tt] = q0 * sv + q1 * cv;
        }
        *(float2*)&qr_s[ch * XQ + t0]       = make_float2(r0[0], r0[1]);
        *(float2*)&qr_s[(ch + 1) * XQ + t0] = make_float2(r1[0], r1[1]);
    }
#pragma unroll
    for (int tt = 0; tt < 2; tt++)
        atomicAdd(&za[(t0 + tt) * 4 + head], zp[tt]);
    __syncthreads();

    // matvec: out[t][e] = sum_d q_rope[t][h*24+d] * kv[h][d][e]
    u64 mv[2][3];
#pragma unroll
    for (int tt = 0; tt < 2; tt++)
#pragma unroll
        for (int jj = 0; jj < 3; jj++) mv[tt][jj] = 0ull;

    const float* qb  = &qr_s[(head * Dd) * XQ + t0];
    const float* kvb = &kv_s[head * KVP + e0];
#pragma unroll 4
    for (int d = 0; d < Dd; d++) {
        float2 qv2 = *(const float2*)(qb + d * XQ);
        const u64* kvr = (const u64*)(kvb + d * Dd);
        u64 w0 = kvr[0], w1 = kvr[1], w2 = kvr[2];
        float qv[2] = {qv2.x, qv2.y};
#pragma unroll
        for (int tt = 0; tt < 2; tt++) {
            u64 xd = pk2(qv[tt], qv[tt]);
            mv[tt][0] = fma2(xd, w0, mv[tt][0]);
            mv[tt][1] = fma2(xd, w1, mv[tt][1]);
            mv[tt][2] = fma2(xd, w2, mv[tt][2]);
        }
    }

    // scale by z/n and store attention term (coalesced)
    float* orow = og + ((size_t)bb * Nc + (size_t)q * TT) * Cc;
#pragma unroll
    for (int tt = 0; tt < 2; tt++) {
        float s = __fdividef(inv_n, za[(t0 + tt) * 4 + head] + 1e-6f);
        float* o = orow + (size_t)(t0 + tt) * Cc + j0;
#pragma unroll
        for (int jj = 0; jj < 3; jj++) {
            float a0, a1; upk2(mv[tt][jj], a0, a1);
            *(float2*)(o + 2 * jj) = make_float2(a0 * s, a1 * s);
        }
    }
}

// ---------------- K3: LePE depthwise 3x3 + bias, RMW on out ----------------
__global__ void __launch_bounds__(NT, 2)
k_lepe(const float* __restrict__ xg, const float* __restrict__ lwg,
       const float* __restrict__ lbg, float* __restrict__ og) {
    int tid = threadIdx.x;
    int r = blockIdx.x, bb = blockIdx.y;
    int g_j = tid & 15, g_t = tid >> 4;
    int j0 = g_j * 6, t0 = g_t * 4;

    const float* xbase = xg + ((size_t)bb * Nc + (size_t)r * WIMG) * Cc;
    bool okm = r > 0, okp = (r + 1) < WIMG;

    float add[4][6];
#pragma unroll
    for (int c6 = 0; c6 < 6; c6++) {
        int ch = j0 + c6;
        float w9[9];
#pragma unroll
        for (int i = 0; i < 9; i++) w9[i] = lwg[ch * 9 + i];
        float lb = lbg[ch];
        float wm[6], wc[6], wp[6];
#pragma unroll
        for (int i = 0; i < 6; i++) {
            int ti = t0 - 1 + i;
            bool in = (unsigned)ti < 128u;
            const float* pc = xbase + (size_t)ti * Cc + ch;
            wc[i] = in ? *pc : 0.f;
            wm[i] = (in && okm) ? pc[-(int)(WIMG * Cc)] : 0.f;
            wp[i] = (in && okp) ? pc[WIMG * Cc] : 0.f;
        }
#pragma unroll
        for (int tt = 0; tt < 4; tt++) {
            add[tt][c6] = w9[0] * wm[tt] + w9[1] * wm[tt + 1] + w9[2] * wm[tt + 2]
                        + w9[3] * wc[tt] + w9[4] * wc[tt + 1] + w9[5] * wc[tt + 2]
                        + w9[6] * wp[tt] + w9[7] * wp[tt + 1] + w9[8] * wp[tt + 2]
                        + lb;
        }
    }

    float* orow = og + ((size_t)bb * Nc + (size_t)r * WIMG) * Cc;
#pragma unroll
    for (int tt = 0; tt < 4; tt++) {
        float* o = orow + (size_t)(t0 + tt) * Cc + j0;
#pragma unroll
        for (int jj = 0; jj < 3; jj++) {
            float2 v = *(float2*)(o + 2 * jj);
            v.x += add[tt][2 * jj];
            v.y += add[tt][2 * jj + 1];
            *(float2*)(o + 2 * jj) = v;
        }
    }
}

// ---------------- launch ----------------
extern "C" void kernel_launch(void* const* d_in, const int* in_sizes, int n_in,
                              void* d_out, int out_size) {
    const float* x    = (const float*)d_in[0];
    const float* qk_w = (const float*)d_in[1];
    const float* qk_b = (const float*)d_in[2];
    const float* lw   = (const float*)d_in[3];
    const float* lb   = (const float*)d_in[4];
    float* out = (float*)d_out;

    cudaFuncSetAttribute(k_stats, cudaFuncAttributeMaxDynamicSharedMemorySize, K1_SMEM);
    cudaFuncSetAttribute(k_out,   cudaFuncAttributeMaxDynamicSharedMemorySize, K2_SMEM);

    void* accp = nullptr;
    cudaGetSymbolAddress(&accp, g_accum);
    cudaMemsetAsync(accp, 0, ACC_SZ * sizeof(float), 0);

    dim3 gridT(NBLK, Bc);
    dim3 gridR(WIMG, Bc);
    k_stats<<<gridT, NT, K1_SMEM>>>(x, qk_w, qk_b);
    k_out<<<gridT, NT, K2_SMEM>>>(x, qk_w, qk_b, out);
    k_lepe<<<gridR, NT>>>(x, lw, lb, out);
}

// round 17
// speedup vs baseline: 1.3852x; 1.3852x over previous
#include <cuda_runtime.h>
#include <math.h>

#define Bc 8
#define Nc 16384
#define Cc 96
#define Hh 4
#define Dd 24
#define WIMG 128
#define NT 512
#define KVP 584          // kv_s per-head pitch

// k_stats pitch: 4-float halo + 128 + pad; 16B-aligned rows, bank stride 12
#define XPS 140
#define HO 4
// k_out pitch: 16B-aligned; qr_s head-padded (QHP) so heads hit banks 0/8/16/24
#define XPO 132
#define QHP 8

// rope: theta_k = 10000^(-k/48); angle = (n mod 128) * theta_k
#define THL 0.27682734124061354f   // log2(10000)/48

// ---- fused global scratch: [0,18432) = kv[b][h][24][24], [18432,19200) = ksum[b][96]
#define ACC_KV 0
#define ACC_KS 18432
#define ACC_SZ 19200
__device__ float g_accum[ACC_SZ];

typedef unsigned long long u64;

__device__ __forceinline__ u64 pk2(float lo, float hi) {
    u64 r; asm("mov.b64 %0,{%1,%2};" : "=l"(r) : "f"(lo), "f"(hi)); return r;
}
__device__ __forceinline__ void upk2(u64 v, float& lo, float& hi) {
    asm("mov.b64 {%0,%1},%2;" : "=f"(lo), "=f"(hi) : "l"(v));
}
__device__ __forceinline__ u64 fma2(u64 a, u64 b, u64 c) {
    u64 d; asm("fma.rn.f32x2 %0,%1,%2,%3;" : "=l"(d) : "l"(a), "l"(b), "l"(c)); return d;
}
__device__ __forceinline__ float elu1(float x) { return x > 0.f ? x + 1.f : __expf(x); }

// ---------------- K1: k-half GEMM + ksum + kv reduction (R13/R15 version) ---------
// smem: x_s[96*XPS] | w_s[9216] | b_s[96] | kr_s[96*XPS]
#define K1_SMEM ((13440 + 9216 + 96 + 13440) * 4)

__global__ void __launch_bounds__(NT, 1)
k_stats(const float* __restrict__ xg, const float* __restrict__ wg,
        const float* __restrict__ bg) {
    extern __shared__ float smem[];
    float* x_s  = smem;            // [c*XPS + HO + t]
    float* w_s  = smem + 13440;    // [c*96 + j]
    float* b_s  = w_s + 9216;
    float* kr_s = b_s + 96;        // [c*XPS + HO + t]

    int tid = threadIdx.x;
    int r = blockIdx.x, b = blockIdx.y;
    const float* xrow = xg + ((size_t)b * Nc + (size_t)r * WIMG) * Cc;

    for (int i = tid; i < WIMG * Cc; i += NT) {
        int t = i / Cc, c = i % Cc;
        x_s[c * XPS + HO + t] = xrow[i];
    }
    for (int i = tid; i < Cc * Cc; i += NT) {
        int j = i / Cc, c = i % Cc;
        w_s[c * Cc + j] = wg[(Cc + j) * Cc + c];
    }
    if (tid < Cc) b_s[tid] = bg[Cc + tid];
    __syncthreads();

    // GEMM: warp owns 6 channels (broadcast w), lane owns 4 consecutive tokens
    int warp = tid >> 5, lane = tid & 31;
    int j0 = warp * 6, t0 = lane * 4;

    u64 acc[4][3];
#pragma unroll
    for (int tt = 0; tt < 4; tt++)
#pragma unroll
        for (int jj = 0; jj < 3; jj++)
            acc[tt][jj] = pk2(b_s[j0 + 2 * jj], b_s[j0 + 2 * jj + 1]);

#pragma unroll 4
    for (int c = 0; c < Cc; c++) {
        float4 xv4 = *(const float4*)&x_s[c * XPS + HO + t0];
        const u64* wr = (const u64*)&w_s[c * Cc + j0];
        u64 w0 = wr[0], w1 = wr[1], w2 = wr[2];
        float xv[4] = {xv4.x, xv4.y, xv4.z, xv4.w};
#pragma unroll
        for (int tt = 0; tt < 4; tt++) {
            u64 xd = pk2(xv[tt], xv[tt]);
            acc[tt][0] = fma2(xd, w0, acc[tt][0]);
            acc[tt][1] = fma2(xd, w1, acc[tt][1]);
            acc[tt][2] = fma2(xd, w2, acc[tt][2]);
        }
    }

    // epilogue: elu+1, rope (MUFU), packed stores, warp-reduced ksum
#pragma unroll
    for (int jj = 0; jj < 3; jj++) {
        int ch = j0 + 2 * jj;
        int kk = ch >> 1;
        float theta = exp2f(-(float)kk * THL);
        float r0[4], r1[4];
        float s0 = 0.f, s1 = 0.f;
#pragma unroll
        for (int tt = 0; tt < 4; tt++) {
            int t = t0 + tt;
            float a0, a1; upk2(acc[tt][jj], a0, a1);
            float k0 = elu1(a0), k1 = elu1(a1);
            s0 += k0; s1 += k1;
            float a = (float)t * theta;
            float sv = __sinf(a), cv = __cosf(a);
            r0[tt] = k0 * cv - k1 * sv;
            r1[tt] = k0 * sv + k1 * cv;
        }
        *(float4*)&kr_s[ch * XPS + HO + t0]       = make_float4(r0[0], r0[1], r0[2], r0[3]);
        *(float4*)&kr_s[(ch + 1) * XPS + HO + t0] = make_float4(r1[0], r1[1], r1[2], r1[3]);
#pragma unroll
        for (int off = 16; off; off >>= 1) {
            s0 += __shfl_xor_sync(0xffffffffu, s0, off);
            s1 += __shfl_xor_sync(0xffffffffu, s1, off);
        }
        if (lane == 0) {
            atomicAdd(&g_accum[ACC_KS + b * Cc + ch], s0);
            atomicAdd(&g_accum[ACC_KS + b * Cc + ch + 1], s1);
        }
    }
    __syncthreads();

    // kv: 4 heads x 128 threads; each thread 3x3 cells over 64 tokens (float4)
    int h = tid >> 7, q = tid & 127;
    int cell = q & 63, half = q >> 6;
    int d0 = (cell & 7) * 3, e0 = (cell >> 3) * 3;
    int tq0 = half * 64;
    u64 a2[3][3];
#pragma unroll
    for (int i = 0; i < 3; i++)
#pragma unroll
        for (int j = 0; j < 3; j++) a2[i][j] = 0ull;

    const float* krb = &kr_s[(h * Dd + d0) * XPS + HO + tq0];
    const float* xb  = &x_s[(h * Dd + e0) * XPS + HO + tq0];
#pragma unroll 2
    for (int i = 0; i < 16; i++) {
        float4 kA = *(const float4*)&krb[4 * i];
        float4 kB = *(const float4*)&krb[XPS + 4 * i];
        float4 kC = *(const float4*)&krb[2 * XPS + 4 * i];
        float4 xA = *(const float4*)&xb[4 * i];
        float4 xB = *(const float4*)&xb[XPS + 4 * i];
        float4 xC = *(const float4*)&xb[2 * XPS + 4 * i];
        u64 kr0a = pk2(kA.x, kA.y), kr0b = pk2(kA.z, kA.w);
        u64 kr1a = pk2(kB.x, kB.y), kr1b = pk2(kB.z, kB.w);
        u64 kr2a = pk2(kC.x, kC.y), kr2b = pk2(kC.z, kC.w);
        u64 xv0a = pk2(xA.x, xA.y), xv0b = pk2(xA.z, xA.w);
        u64 xv1a = pk2(xB.x, xB.y), xv1b = pk2(xB.z, xB.w);
        u64 xv2a = pk2(xC.x, xC.y), xv2b = pk2(xC.z, xC.w);
        a2[0][0] = fma2(kr0a, xv0a, a2[0][0]); a2[0][0] = fma2(kr0b, xv0b, a2[0][0]);
        a2[0][1] = fma2(kr0a, xv1a, a2[0][1]); a2[0][1] = fma2(kr0b, xv1b, a2[0][1]);
        a2[0][2] = fma2(kr0a, xv2a, a2[0][2]); a2[0][2] = fma2(kr0b, xv2b, a2[0][2]);
        a2[1][0] = fma2(kr1a, xv0a, a2[1][0]); a2[1][0] = fma2(kr1b, xv0b, a2[1][0]);
        a2[1][1] = fma2(kr1a, xv1a, a2[1][1]); a2[1][1] = fma2(kr1b, xv1b, a2[1][1]);
        a2[1][2] = fma2(kr1a, xv2a, a2[1][2]); a2[1][2] = fma2(kr1b, xv2b, a2[1][2]);
        a2[2][0] = fma2(kr2a, xv0a, a2[2][0]); a2[2][0] = fma2(kr2b, xv0b, a2[2][0]);
        a2[2][1] = fma2(kr2a, xv1a, a2[2][1]); a2[2][1] = fma2(kr2b, xv1b, a2[2][1]);
        a2[2][2] = fma2(kr2a, xv2a, a2[2][2]); a2[2][2] = fma2(kr2b, xv2b, a2[2][2]);
    }
    float* kvb_g = &g_accum[ACC_KV + ((size_t)b * Hh + h) * Dd * Dd];
#pragma unroll
    for (int i = 0; i < 3; i++)
#pragma unroll
        for (int j = 0; j < 3; j++) {
            float lo, hi; upk2(a2[i][j], lo, hi);
            atomicAdd(&kvb_g[(d0 + i) * Dd + e0 + j], lo + hi);
        }
}

// ---------------- K2: q-half GEMM (warp-ch) + z + matvec + store (NO LePE) --------
// smem: x_s[96*XPO] | w_s[9216] | qr_s[96*XPO + 4*QHP] | kv_s[4*KVP] | b_s[96] | za[512]
#define QR_SZ (Cc * XPO + Hh * QHP)
#define K2_SMEM ((Cc * XPO + 9216 + QR_SZ + 4 * KVP + 96 + 512) * 4)

__global__ void __launch_bounds__(NT, 1)
k_out(const float* __restrict__ xg, const float* __restrict__ wg,
      const float* __restrict__ bg, float* __restrict__ og) {
    extern __shared__ float smem[];
    float* x_s  = smem;                 // [c*XPO + t]
    float* w_s  = smem + Cc * XPO;      // [c*96 + j]
    float* qr_s = w_s + 9216;           // [ch*XPO + (ch/24)*QHP + t]
    float* kv_s = qr_s + QR_SZ;         // [4][KVP]
    float* b_s  = kv_s + 4 * KVP;
    float* za   = b_s + 96;             // [128][4]

    int tid = threadIdx.x;
    int r = blockIdx.x, bb = blockIdx.y;
    const float* xrow = xg + ((size_t)bb * Nc + (size_t)r * WIMG) * Cc;

    for (int i = tid; i < WIMG * Cc; i += NT) {
        int t = i / Cc, c = i % Cc;
        x_s[c * XPO + t] = xrow[i];
    }
    for (int i = tid; i < Cc * Cc; i += NT) {
        int j = i / Cc, c = i % Cc;
        w_s[c * Cc + j] = wg[j * Cc + c];
    }
    if (tid < Cc) b_s[tid] = bg[tid];
    if (tid < 512) za[tid] = 0.f;
    for (int i = tid; i < Hh * Dd * Dd; i += NT)
        kv_s[(i / 576) * KVP + (i % 576)] =
            g_accum[ACC_KV + (size_t)bb * Hh * Dd * Dd + i];
    __syncthreads();

    const float inv_n = 1.f / (float)Nc;

    // ---- GEMM phase: warp owns 6 channels (broadcast w), lane owns 4 tokens ----
    {
        int warp = tid >> 5, lane = tid & 31;
        int j0 = warp * 6, t0 = lane * 4;
        int headw = warp >> 2;
        float* qr_h = qr_s + headw * QHP;

        u64 acc[4][3];
#pragma unroll
        for (int tt = 0; tt < 4; tt++)
#pragma unroll
            for (int jj = 0; jj < 3; jj++)
                acc[tt][jj] = pk2(b_s[j0 + 2 * jj], b_s[j0 + 2 * jj + 1]);

#pragma unroll 4
        for (int c = 0; c < Cc; c++) {
            float4 xv4 = *(const float4*)&x_s[c * XPO + t0];
            const u64* wr = (const u64*)&w_s[c * Cc + j0];
            u64 w0 = wr[0], w1 = wr[1], w2 = wr[2];
            float xv[4] = {xv4.x, xv4.y, xv4.z, xv4.w};
#pragma unroll
            for (int tt = 0; tt < 4; tt++) {
                u64 xd = pk2(xv[tt], xv[tt]);
                acc[tt][0] = fma2(xd, w0, acc[tt][0]);
                acc[tt][1] = fma2(xd, w1, acc[tt][1]);
                acc[tt][2] = fma2(xd, w2, acc[tt][2]);
            }
        }

        // epilogue: elu+1, z partial vs k_mean, rope (MUFU), packed q_rope stores
        float km[6];
#pragma unroll
        for (int i = 0; i < 6; i++) km[i] = g_accum[ACC_KS + bb * Cc + j0 + i] * inv_n;

        float zp[4] = {0.f, 0.f, 0.f, 0.f};
#pragma unroll
        for (int jj = 0; jj < 3; jj++) {
            int ch = j0 + 2 * jj;
            int kk = ch >> 1;
            float theta = exp2f(-(float)kk * THL);
            float r0[4], r1[4];
#pragma unroll
            for (int tt = 0; tt < 4; tt++) {
                int t = t0 + tt;
                float a0, a1; upk2(acc[tt][jj], a0, a1);
                float q0 = elu1(a0), q1 = elu1(a1);
                zp[tt] += q0 * km[2 * jj] + q1 * km[2 * jj + 1];
                float a = (float)t * theta;
                float sv = __sinf(a), cv = __cosf(a);
                r0[tt] = q0 * cv - q1 * sv;
                r1[tt] = q0 * sv + q1 * cv;
            }
            *(float4*)&qr_h[ch * XPO + t0]       = make_float4(r0[0], r0[1], r0[2], r0[3]);
            *(float4*)&qr_h[(ch + 1) * XPO + t0] = make_float4(r1[0], r1[1], r1[2], r1[3]);
        }
#pragma unroll
        for (int tt = 0; tt < 4; tt++)
            atomicAdd(&za[(t0 + tt) * 4 + headw], zp[tt]);
    }
    __syncthreads();

    // ---- output phase: j-fastest (coalesced stores; head-padded qr conflict-free) --
    int g_j = tid & 15, g_t = tid >> 4;
    int j0 = g_j * 6, t0 = g_t * 4;
    int head = j0 / Dd, e0 = j0 % Dd;

    u64 mv[4][3];
#pragma unroll
    for (int tt = 0; tt < 4; tt++)
#pragma unroll
        for (int jj = 0; jj < 3; jj++) mv[tt][jj] = 0ull;

    const float* qb  = &qr_s[(head * Dd) * XPO + head * QHP + t0];
    const float* kvb = &kv_s[head * KVP + e0];
#pragma unroll 4
    for (int d = 0; d < Dd; d++) {
        float4 qv4 = *(const float4*)(qb + d * XPO);
        const u64* kvr = (const u64*)(kvb + d * Dd);
        u64 w0 = kvr[0], w1 = kvr[1], w2 = kvr[2];
        float qv[4] = {qv4.x, qv4.y, qv4.z, qv4.w};
#pragma unroll
        for (int tt = 0; tt < 4; tt++) {
            u64 xd = pk2(qv[tt], qv[tt]);
            mv[tt][0] = fma2(xd, w0, mv[tt][0]);
            mv[tt][1] = fma2(xd, w1, mv[tt][1]);
            mv[tt][2] = fma2(xd, w2, mv[tt][2]);
        }
    }

    // scale by z/n and store attention term (coalesced)
    float* orow = og + ((size_t)bb * Nc + (size_t)r * WIMG) * Cc;
#pragma unroll
    for (int tt = 0; tt < 4; tt++) {
        float s = __fdividef(inv_n, za[(t0 + tt) * 4 + head] + 1e-6f);
        float* o = orow + (size_t)(t0 + tt) * Cc + j0;
#pragma unroll
        for (int jj = 0; jj < 3; jj++) {
            float a0, a1; upk2(mv[tt][jj], a0, a1);
            *(float2*)(o + 2 * jj) = make_float2(a0 * s, a1 * s);
        }
    }
}

// ---------------- K3: LePE depthwise 3x3 + bias, RMW on out ----------------
__global__ void __launch_bounds__(NT, 2)
k_lepe(const float* __restrict__ xg, const float* __restrict__ lwg,
       const float* __restrict__ lbg, float* __restrict__ og) {
    int tid = threadIdx.x;
    int r = blockIdx.x, bb = blockIdx.y;
    int g_j = tid & 15, g_t = tid >> 4;
    int j0 = g_j * 6, t0 = g_t * 4;

    const float* xbase = xg + ((size_t)bb * Nc + (size_t)r * WIMG) * Cc;
    bool okm = r > 0, okp = (r + 1) < WIMG;

    float add[4][6];
#pragma unroll
    for (int c6 = 0; c6 < 6; c6++) {
        int ch = j0 + c6;
        float w9[9];
#pragma unroll
        for (int i = 0; i < 9; i++) w9[i] = lwg[ch * 9 + i];
        float lb = lbg[ch];
        float wm[6], wc[6], wp[6];
#pragma unroll
        for (int i = 0; i < 6; i++) {
            int ti = t0 - 1 + i;
            bool in = (unsigned)ti < 128u;
            const float* pc = xbase + (size_t)ti * Cc + ch;
            wc[i] = in ? *pc : 0.f;
            wm[i] = (in && okm) ? pc[-(int)(WIMG * Cc)] : 0.f;
            wp[i] = (in && okp) ? pc[WIMG * Cc] : 0.f;
        }
#pragma unroll
        for (int tt = 0; tt < 4; tt++) {
            add[tt][c6] = w9[0] * wm[tt] + w9[1] * wm[tt + 1] + w9[2] * wm[tt + 2]
                        + w9[3] * wc[tt] + w9[4] * wc[tt + 1] + w9[5] * wc[tt + 2]
                        + w9[6] * wp[tt] + w9[7] * wp[tt + 1] + w9[8] * wp[tt + 2]
                        + lb;
        }
    }

    float* orow = og + ((size_t)bb * Nc + (size_t)r * WIMG) * Cc;
#pragma unroll
    for (int tt = 0; tt < 4; tt++) {
        float* o = orow + (size_t)(t0 + tt) * Cc + j0;
#pragma unroll
        for (int jj = 0; jj < 3; jj++) {
            float2 v = *(float2*)(o + 2 * jj);
            v.x += add[tt][2 * jj];
            v.y += add[tt][2 * jj + 1];
            *(float2*)(o + 2 * jj) = v;
        }
    }
}

// ---------------- launch ----------------
extern "C" void kernel_launch(void* const* d_in, const int* in_sizes, int n_in,
                              void* d_out, int out_size) {
    const float* x    = (const float*)d_in[0];
    const float* qk_w = (const float*)d_in[1];
    const float* qk_b = (const float*)d_in[2];
    const float* lw   = (const float*)d_in[3];
    const float* lb   = (const float*)d_in[4];
    float* out = (float*)d_out;

    cudaFuncSetAttribute(k_stats, cudaFuncAttributeMaxDynamicSharedMemorySize, K1_SMEM);
    cudaFuncSetAttribute(k_out,   cudaFuncAttributeMaxDynamicSharedMemorySize, K2_SMEM);

    void* accp = nullptr;
    cudaGetSymbolAddress(&accp, g_accum);
    cudaMemsetAsync(accp, 0, ACC_SZ * sizeof(float), 0);

    dim3 grid(WIMG, Bc);
    k_stats<<<grid, NT, K1_SMEM>>>(x, qk_w, qk_b);
    k_out<<<grid, NT, K2_SMEM>>>(x, qk_w, qk_b, out);
    k_lepe<<<grid, NT>>>(x, lw, lb, out);
}